// round 12
// baseline (speedup 1.0000x reference)
#include <cuda_runtime.h>
#include <cuda_fp16.h>
#include <cstdint>

#define NN    50000
#define EE    1600000
#define KP    25
#define KALL  26                    // 25 spline mats + root
#define FOUT  64
#define KROW  (KALL * FOUT)         // 1664 halves per node row
#define PADR  72                    // row pad (half): 144B rows, LDSM conflict-free
#define NBLK  ((NN + 1023) / 1024)  // scan blocks

// ---------------- device scratch (no runtime allocation allowed) -----------
__device__ __half g_xh[(size_t)NN * 64];
__device__ __half g_wt[KALL * 64 * 64];          // fp16 W^T: [k][o][i], k=25 is root
__device__ __half g_xw[(size_t)NN * KROW];       // 166 MB fp16 table
__device__ int    g_degi[NN];                    // zero-init; reset by final_kernel
__device__ int    g_cnt[NN];                     // zero-init; reset by scan_kernel
__device__ int    g_off[NN];
__device__ int    g_bsum[NBLK];
__device__ int    g_tick;                        // zero-init; reset by scan_kernel
__device__ uint4  g_erec[EE];                    // edge records (col-sorted)

// ---------------- helpers ---------------------------------------------------
__device__ __forceinline__ uint32_t smem_u32(const void* p) {
    uint32_t a;
    asm("{ .reg .u64 t; cvta.to.shared.u64 t, %1; cvt.u32.u64 %0, t; }"
        : "=r"(a) : "l"(p));
    return a;
}
__device__ __forceinline__ void ldsm_x4(uint32_t addr, uint32_t* r) {
    asm volatile("ldmatrix.sync.aligned.m8n8.x4.shared.b16 {%0,%1,%2,%3}, [%4];"
                 : "=r"(r[0]), "=r"(r[1]), "=r"(r[2]), "=r"(r[3]) : "r"(addr));
}
__device__ __forceinline__ void mma_f16(float* c, const uint32_t* a, const uint32_t* b) {
    asm volatile(
        "mma.sync.aligned.m16n8k16.row.col.f32.f16.f16.f32 "
        "{%0,%1,%2,%3}, {%4,%5,%6,%7}, {%8,%9}, {%0,%1,%2,%3};"
        : "+f"(c[0]), "+f"(c[1]), "+f"(c[2]), "+f"(c[3])
        : "r"(a[0]), "r"(a[1]), "r"(a[2]), "r"(a[3]), "r"(b[0]), "r"(b[1]));
}

// ---------------------------------------------------------------------------
// fused prep (launch 0): x->fp16, out zero, W^T->fp16, col+row histograms.
// g_cnt and g_degi are zero at entry (zero-init / reset by scan & final).
// ---------------------------------------------------------------------------
__global__ __launch_bounds__(256) void fused_prep(const float* __restrict__ x,
                                                  const float* __restrict__ w,
                                                  const float* __restrict__ root,
                                                  const int*   __restrict__ ei,
                                                  float* __restrict__ out) {
    int i = blockIdx.x * blockDim.x + threadIdx.x;
    if (i < NN * 64) {
        g_xh[i] = __float2half(x[i]);
        out[i] = 0.0f;
    }
    if (i < KALL * 64 * 64) {
        int k = i >> 12, rem = i & 4095;
        int ii = rem >> 6, o = rem & 63;
        float v = (k < KP) ? w[i] : root[rem];
        g_wt[(k << 12) + (o << 6) + ii] = __float2half(v);   // [k][o][i]
    }
    if (i < EE) {
        atomicAdd(&g_cnt[ei[EE + i]], 1);    // col histogram (sort)
        atomicAdd(&g_degi[ei[i]], 1);        // row histogram (degree)
    }
}

// ---------------------------------------------------------------------------
// scan (launch 1): per-block shuffle scan + cnt reset; last block scans tops.
// ---------------------------------------------------------------------------
__global__ __launch_bounds__(1024) void scan_kernel() {
    __shared__ int wsum[32];
    __shared__ int tops[NBLK];
    __shared__ int amLast;
    int idx  = blockIdx.x * 1024 + threadIdx.x;
    int lane = threadIdx.x & 31;
    int wid  = threadIdx.x >> 5;
    int v = (idx < NN) ? g_cnt[idx] : 0;
    if (idx < NN) g_cnt[idx] = 0;                // reset for next replay
    int s = v;
    #pragma unroll
    for (int o = 1; o < 32; o <<= 1) {
        int t = __shfl_up_sync(0xFFFFFFFFu, s, o);
        if (lane >= o) s += t;
    }
    if (lane == 31) wsum[wid] = s;
    __syncthreads();
    if (wid == 0) {
        int ws = wsum[lane];
        #pragma unroll
        for (int o = 1; o < 32; o <<= 1) {
            int t = __shfl_up_sync(0xFFFFFFFFu, ws, o);
            if (lane >= o) ws += t;
        }
        wsum[lane] = ws;
    }
    __syncthreads();
    int excl = s - v + (wid > 0 ? wsum[wid - 1] : 0);
    if (idx < NN) g_off[idx] = excl;             // block-local exclusive prefix
    if (threadIdx.x == 1023) g_bsum[blockIdx.x] = excl + v;

    // last-finishing block scans the 49 block totals
    __threadfence();
    if (threadIdx.x == 0)
        amLast = (atomicAdd(&g_tick, 1) == (int)gridDim.x - 1);
    __syncthreads();
    if (amLast) {
        if (threadIdx.x < NBLK) tops[threadIdx.x] = g_bsum[threadIdx.x];
        __syncthreads();
        if (threadIdx.x == 0) {
            int acc = 0;
            #pragma unroll 1
            for (int i2 = 0; i2 < NBLK; i2++) { int t = tops[i2]; tops[i2] = acc; acc += t; }
            g_tick = 0;                          // reset for next replay
        }
        __syncthreads();
        if (threadIdx.x < NBLK) g_bsum[threadIdx.x] = tops[threadIdx.x];
    }
}

// ---------------------------------------------------------------------------
// prep_edges (launch 2): 4 edges/thread, batched loads, col-sorted scatter.
// ---------------------------------------------------------------------------
__global__ __launch_bounds__(256) void prep_edges(const int* __restrict__ ei,
                                                  const float* __restrict__ ps) {
    int e0 = (blockIdx.x * 256 + threadIdx.x) * 4;
    if (e0 >= EE) return;
    int4   rows = *(const int4*)(ei + e0);
    int4   cols = *(const int4*)(ei + EE + e0);
    float4 pa   = *(const float4*)(ps + 2 * e0);
    float4 pb   = *(const float4*)(ps + 2 * e0 + 4);

    int   rr[4] = {rows.x, rows.y, rows.z, rows.w};
    int   cc[4] = {cols.x, cols.y, cols.z, cols.w};
    float px[4] = {pa.x, pa.z, pb.x, pb.z};
    float py[4] = {pa.y, pa.w, pb.y, pb.w};

    uint4 rec[4];
    int   slot[4];
    #pragma unroll
    for (int q = 0; q < 4; q++) {
        float v0 = px[q] * 4.0f, v1 = py[q] * 4.0f;
        float fl0 = floorf(v0), fl1 = floorf(v1);
        float f0 = v0 - fl0, f1 = v1 - fl1;
        int i0 = (int)fl0, i1 = (int)fl1;        // 0..3, +1 in range
        unsigned c00 = (unsigned)(i0 * 5 + i1);
        unsigned cells = c00 | ((c00 + 5u) << 8) | ((c00 + 1u) << 16) | ((c00 + 6u) << 24);
        __half2 fh = __floats2half2_rn(f0, f1);
        rec[q].x = (unsigned)(rr[q] * FOUT);
        rec[q].y = (unsigned)(cc[q] * KROW);
        rec[q].z = cells;
        rec[q].w = *(unsigned*)&fh;
        slot[q] = atomicAdd(&g_off[cc[q]], 1) + g_bsum[cc[q] >> 10];
    }
    #pragma unroll
    for (int q = 0; q < 4; q++)
        g_erec[slot[q]] = rec[q];
}

// ---------------------------------------------------------------------------
// xw_mma (launch 3 <- ncu): xw[n,k,:] = x[n,:] @ W[k]; 512 thr, 256-node tiles
// ---------------------------------------------------------------------------
__global__ __launch_bounds__(512) void xw_mma() {
    extern __shared__ __half sm[];
    __half* xs = sm;                   // [256][PADR]; reused as epilogue stage
    __half* ws = sm + 256 * PADR;      // [64][PADR]

    const int tid  = threadIdx.x;
    const int wid  = tid >> 5;
    const int lane = tid & 31;
    const int n0   = blockIdx.x * 256;
    const int kbeg = blockIdx.y * 5;
    const int kcnt = (blockIdx.y == 5) ? 1 : 5;

    #pragma unroll
    for (int it = 0; it < 4; it++) {
        int flat = tid + 512 * it;
        int r = flat >> 3, j = flat & 7;
        int gn = n0 + r;
        uint4 v = make_uint4(0, 0, 0, 0);
        if (gn < NN) v = *(const uint4*)(g_xh + (size_t)gn * 64 + j * 8);
        *(uint4*)(xs + r * PADR + j * 8) = v;
    }
    __syncthreads();

    const int m0    = wid * 16;
    const int a_row = m0 + (lane & 15);
    const int a_c8  = (lane >> 4) * 8;
    uint32_t ah[4][4];
    #pragma unroll
    for (int ks = 0; ks < 4; ks++)
        ldsm_x4(smem_u32(xs + a_row * PADR + ks * 16 + a_c8), ah[ks]);

    const int bw_r = lane & 7;
    const int bw_g = lane >> 3;
    const int g  = lane >> 2;
    const int t2 = (lane & 3) * 2;

    for (int j = 0; j < kcnt; j++) {
        const int k = kbeg + j;
        __syncthreads();
        {
            int r = tid >> 3, jc = tid & 7;
            *(uint4*)(ws + r * PADR + jc * 8) =
                *(const uint4*)(g_wt + (k << 12) + r * 64 + jc * 8);
        }
        __syncthreads();

        #pragma unroll
        for (int nt = 0; nt < 8; nt++) {
            float acc[4] = {0.f, 0.f, 0.f, 0.f};
            uint32_t bh[8];
            uint32_t row_off = (nt * 8 + bw_r) * PADR + bw_g * 8;
            ldsm_x4(smem_u32(ws + row_off), bh);
            ldsm_x4(smem_u32(ws + row_off + 32), bh + 4);
            #pragma unroll
            for (int ks = 0; ks < 4; ks++)
                mma_f16(acc, ah[ks], bh + ks * 2);
            __half2 h01 = __floats2half2_rn(acc[0], acc[1]);
            __half2 h23 = __floats2half2_rn(acc[2], acc[3]);
            *(__half2*)(xs + (m0 + g) * PADR + nt * 8 + t2)     = h01;
            *(__half2*)(xs + (m0 + g + 8) * PADR + nt * 8 + t2) = h23;
        }
        __syncthreads();
        #pragma unroll
        for (int it = 0; it < 4; it++) {
            int flat = tid + 512 * it;
            int r = flat >> 3, jc = flat & 7;
            int gn = n0 + r;
            if (gn < NN)
                *(uint4*)(g_xw + (size_t)gn * KROW + k * 64 + jc * 8) =
                    *(const uint4*)(xs + r * PADR + jc * 8);
        }
    }
}

// ---------------------------------------------------------------------------
// edge pass (launch 4): 4 edges/warp (2 per half-warp, batched loads)
// ---------------------------------------------------------------------------
__global__ __launch_bounds__(256) void edge_kernel(float* __restrict__ out) {
    const int warp   = (blockIdx.x * blockDim.x + threadIdx.x) >> 5;
    const int lane   = threadIdx.x & 31;
    const int half   = lane >> 4;
    const int sub4   = (lane & 15) * 4;
    const int nwarps = (gridDim.x * blockDim.x) >> 5;

    for (int e4 = warp * 4; e4 < EE; e4 += nwarps * 4) {
        uint4 ra = g_erec[e4 + half];
        uint4 rb = g_erec[e4 + 2 + half];

        const __half* pa = g_xw + ra.y + sub4;
        const __half* pb = g_xw + rb.y + sub4;
        unsigned ca = ra.z, cb = rb.z;

        uint2 Aa = *(const uint2*)(pa + ((ca & 255u) << 6));
        uint2 Ba = *(const uint2*)(pa + (((ca >> 8) & 255u) << 6));
        uint2 Ca = *(const uint2*)(pa + (((ca >> 16) & 255u) << 6));
        uint2 Da = *(const uint2*)(pa + ((ca >> 24) << 6));
        uint2 Ab = *(const uint2*)(pb + ((cb & 255u) << 6));
        uint2 Bb = *(const uint2*)(pb + (((cb >> 8) & 255u) << 6));
        uint2 Cb = *(const uint2*)(pb + (((cb >> 16) & 255u) << 6));
        uint2 Db = *(const uint2*)(pb + ((cb >> 24) << 6));

        {
            __half2 fh = *(const __half2*)&ra.w;
            float f0 = __low2float(fh), f1 = __high2float(fh);
            float g0 = 1.0f - f0, g1 = 1.0f - f1;
            __half2 w00 = __float2half2_rn(g0 * g1);
            __half2 w10 = __float2half2_rn(f0 * g1);
            __half2 w01 = __float2half2_rn(g0 * f1);
            __half2 w11 = __float2half2_rn(f0 * f1);
            __half2 r0 = __hmul2(w00, *(__half2*)&Aa.x);
            r0 = __hfma2(w10, *(__half2*)&Ba.x, r0);
            r0 = __hfma2(w01, *(__half2*)&Ca.x, r0);
            r0 = __hfma2(w11, *(__half2*)&Da.x, r0);
            __half2 r1 = __hmul2(w00, *(__half2*)&Aa.y);
            r1 = __hfma2(w10, *(__half2*)&Ba.y, r1);
            r1 = __hfma2(w01, *(__half2*)&Ca.y, r1);
            r1 = __hfma2(w11, *(__half2*)&Da.y, r1);
            float2 lo = __half22float2(r0);
            float2 hi = __half22float2(r1);
            float* op = out + ra.x + sub4;
            asm volatile("red.global.add.v4.f32 [%0], {%1, %2, %3, %4};"
                         :: "l"(op), "f"(lo.x), "f"(lo.y), "f"(hi.x), "f"(hi.y)
                         : "memory");
        }
        {
            __half2 fh = *(const __half2*)&rb.w;
            float f0 = __low2float(fh), f1 = __high2float(fh);
            float g0 = 1.0f - f0, g1 = 1.0f - f1;
            __half2 w00 = __float2half2_rn(g0 * g1);
            __half2 w10 = __float2half2_rn(f0 * g1);
            __half2 w01 = __float2half2_rn(g0 * f1);
            __half2 w11 = __float2half2_rn(f0 * f1);
            __half2 r0 = __hmul2(w00, *(__half2*)&Ab.x);
            r0 = __hfma2(w10, *(__half2*)&Bb.x, r0);
            r0 = __hfma2(w01, *(__half2*)&Cb.x, r0);
            r0 = __hfma2(w11, *(__half2*)&Db.x, r0);
            __half2 r1 = __hmul2(w00, *(__half2*)&Ab.y);
            r1 = __hfma2(w10, *(__half2*)&Bb.y, r1);
            r1 = __hfma2(w01, *(__half2*)&Cb.y, r1);
            r1 = __hfma2(w11, *(__half2*)&Db.y, r1);
            float2 lo = __half22float2(r0);
            float2 hi = __half22float2(r1);
            float* op = out + rb.x + sub4;
            asm volatile("red.global.add.v4.f32 [%0], {%1, %2, %3, %4};"
                         :: "l"(op), "f"(lo.x), "f"(lo.y), "f"(hi.x), "f"(hi.y)
                         : "memory");
        }
    }
}

// ---------------------------------------------------------------------------
// final (launch 5): out = out/max(deg,1) + xw[n,25,:] + bias; resets g_degi
// ---------------------------------------------------------------------------
__global__ __launch_bounds__(256) void final_kernel(const float* __restrict__ bias,
                                                    float* __restrict__ out) {
    int i = blockIdx.x * 256 + threadIdx.x;
    if (i >= NN * 16) return;
    int n  = i >> 4;
    int c4 = (i & 15) * 4;
    int d = g_degi[n];
    __syncwarp();                                 // all readers before reset
    if ((i & 15) == 0) g_degi[n] = 0;             // reset for next replay
    float scale = 1.0f / (float)max(d, 1);
    float4 o = *(float4*)(out + n * FOUT + c4);
    uint2 hu = *(const uint2*)(g_xw + (size_t)n * KROW + KP * 64 + c4);
    float2 rl = __half22float2(*(__half2*)&hu.x);
    float2 rh = __half22float2(*(__half2*)&hu.y);
    float4 b = *(const float4*)(bias + c4);
    o.x = o.x * scale + rl.x + b.x;
    o.y = o.y * scale + rl.y + b.y;
    o.z = o.z * scale + rh.x + b.z;
    o.w = o.w * scale + rh.y + b.w;
    *(float4*)(out + n * FOUT + c4) = o;
}

// ---------------------------------------------------------------------------
extern "C" void kernel_launch(void* const* d_in, const int* in_sizes, int n_in,
                              void* d_out, int out_size) {
    const float* x      = (const float*)d_in[0];
    const int*   ei     = (const int*)  d_in[1];
    const float* pseudo = (const float*)d_in[2];
    const float* weight = (const float*)d_in[3];
    const float* root   = (const float*)d_in[4];
    const float* bias   = (const float*)d_in[5];
    float* out = (float*)d_out;

    const int smem_bytes = (256 * PADR + 64 * PADR) * (int)sizeof(__half);
    cudaFuncSetAttribute(xw_mma, cudaFuncAttributeMaxDynamicSharedMemorySize, smem_bytes);

    fused_prep<<<(NN * 64 + 255) / 256, 256>>>(x, weight, root, ei, out);  // 0
    scan_kernel<<<NBLK, 1024>>>();                                         // 1
    prep_edges<<<(EE / 4 + 255) / 256, 256>>>(ei, pseudo);                 // 2

    dim3 g2((NN + 255) / 256, 6);
    xw_mma<<<g2, 512, smem_bytes>>>();                                     // 3 <- ncu

    edge_kernel<<<6144, 256>>>(out);                                       // 4

    final_kernel<<<(NN * 16 + 255) / 256, 256>>>(bias, out);               // 5
}

// round 13
// speedup vs baseline: 1.0620x; 1.0620x over previous
#include <cuda_runtime.h>
#include <cuda_fp16.h>
#include <cstdint>

#define NN    50000
#define EE    1600000
#define KP    25
#define KALL  26                    // 25 spline mats + root
#define FOUT  64
#define KROW  (KALL * FOUT)         // 1664 halves per node row
#define PADR  72                    // row pad (half): 144B rows, LDSM conflict-free
#define NBLK  ((NN + 1023) / 1024)  // scan blocks

// ---------------- device scratch (no runtime allocation allowed) -----------
__device__ __half g_xh[(size_t)NN * 64];
__device__ __half g_wt[KALL * 64 * 64];          // fp16 W^T: [k][o][i], k=25 is root
__device__ __half g_xw[(size_t)NN * KROW];       // 166 MB fp16 table
__device__ float  g_deg[NN];
__device__ int    g_cnt[NN];                     // zero-init; re-zeroed by scan_local
__device__ int    g_off[NN];
__device__ int    g_bsum[NBLK];
__device__ uint4  g_erec[EE];                    // edge records (col-sorted)

// ---------------- helpers ---------------------------------------------------
__device__ __forceinline__ uint32_t smem_u32(const void* p) {
    uint32_t a;
    asm("{ .reg .u64 t; cvta.to.shared.u64 t, %1; cvt.u32.u64 %0, t; }"
        : "=r"(a) : "l"(p));
    return a;
}
__device__ __forceinline__ void ldsm_x4(uint32_t addr, uint32_t* r) {
    asm volatile("ldmatrix.sync.aligned.m8n8.x4.shared.b16 {%0,%1,%2,%3}, [%4];"
                 : "=r"(r[0]), "=r"(r[1]), "=r"(r[2]), "=r"(r[3]) : "r"(addr));
}
__device__ __forceinline__ void mma_f16(float* c, const uint32_t* a, const uint32_t* b) {
    asm volatile(
        "mma.sync.aligned.m16n8k16.row.col.f32.f16.f16.f32 "
        "{%0,%1,%2,%3}, {%4,%5,%6,%7}, {%8,%9}, {%0,%1,%2,%3};"
        : "+f"(c[0]), "+f"(c[1]), "+f"(c[2]), "+f"(c[3])
        : "r"(a[0]), "r"(a[1]), "r"(a[2]), "r"(a[3]), "r"(b[0]), "r"(b[1]));
}

// ---------------------------------------------------------------------------
// fused prep (launch 0): x->fp16, out zero, deg zero, W^T->fp16, col histogram
// ---------------------------------------------------------------------------
__global__ __launch_bounds__(256) void fused_prep(const float* __restrict__ x,
                                                  const float* __restrict__ w,
                                                  const float* __restrict__ root,
                                                  const int*   __restrict__ ei,
                                                  float* __restrict__ out) {
    int i = blockIdx.x * blockDim.x + threadIdx.x;
    if (i < NN * 64) {
        g_xh[i] = __float2half(x[i]);
        out[i] = 0.0f;
    }
    if (i < NN) g_deg[i] = 0.0f;
    if (i < KALL * 64 * 64) {
        int k = i >> 12, rem = i & 4095;
        int ii = rem >> 6, o = rem & 63;
        float v = (k < KP) ? w[i] : root[rem];
        g_wt[(k << 12) + (o << 6) + ii] = __float2half(v);   // [k][o][i]
    }
    if (i < EE) atomicAdd(&g_cnt[ei[EE + i]], 1);
}

// ---- scan (launches 1,2): local shuffle scan (+cnt reset) -> tops scan ----
__global__ __launch_bounds__(1024) void scan_local() {
    __shared__ int wsum[32];
    int idx  = blockIdx.x * 1024 + threadIdx.x;
    int lane = threadIdx.x & 31;
    int wid  = threadIdx.x >> 5;
    int v = (idx < NN) ? g_cnt[idx] : 0;
    if (idx < NN) g_cnt[idx] = 0;                // reset for next launch/replay
    int s = v;
    #pragma unroll
    for (int o = 1; o < 32; o <<= 1) {
        int t = __shfl_up_sync(0xFFFFFFFFu, s, o);
        if (lane >= o) s += t;
    }
    if (lane == 31) wsum[wid] = s;
    __syncthreads();
    if (wid == 0) {
        int ws = wsum[lane];
        #pragma unroll
        for (int o = 1; o < 32; o <<= 1) {
            int t = __shfl_up_sync(0xFFFFFFFFu, ws, o);
            if (lane >= o) ws += t;
        }
        wsum[lane] = ws;
    }
    __syncthreads();
    int excl = s - v + (wid > 0 ? wsum[wid - 1] : 0);
    if (idx < NN) g_off[idx] = excl;             // block-local exclusive prefix
    if (threadIdx.x == 1023) g_bsum[blockIdx.x] = excl + v;
}
__global__ __launch_bounds__(64) void scan_tops() {
    __shared__ int s[64];
    int tid = threadIdx.x;
    s[tid] = (tid < NBLK) ? g_bsum[tid] : 0;
    __syncthreads();
    if (tid == 0) {
        int acc = 0;
        #pragma unroll 1
        for (int i = 0; i < NBLK; i++) { int t = s[i]; s[i] = acc; acc += t; }
    }
    __syncthreads();
    if (tid < NBLK) g_bsum[tid] = s[tid];
}

// ---------------------------------------------------------------------------
// prep_edges (launch 3 <- ncu): 2 edges/thread, batched loads, sorted scatter.
// ---------------------------------------------------------------------------
__global__ __launch_bounds__(256) void prep_edges(const int* __restrict__ ei,
                                                  const float* __restrict__ ps) {
    int e0 = (blockIdx.x * 256 + threadIdx.x) * 2;
    if (e0 >= EE) return;
    int2   rows = *(const int2*)(ei + e0);
    int2   cols = *(const int2*)(ei + EE + e0);
    float4 pp   = *(const float4*)(ps + 2 * e0);

    int   rr[2] = {rows.x, rows.y};
    int   cc[2] = {cols.x, cols.y};
    float px[2] = {pp.x, pp.z};
    float py[2] = {pp.y, pp.w};

    uint4 rec[2];
    int   slot[2];
    #pragma unroll
    for (int q = 0; q < 2; q++) {
        float v0 = px[q] * 4.0f, v1 = py[q] * 4.0f;
        float fl0 = floorf(v0), fl1 = floorf(v1);
        float f0 = v0 - fl0, f1 = v1 - fl1;
        int i0 = (int)fl0, i1 = (int)fl1;        // 0..3, +1 in range
        unsigned c00 = (unsigned)(i0 * 5 + i1);
        unsigned cells = c00 | ((c00 + 5u) << 8) | ((c00 + 1u) << 16) | ((c00 + 6u) << 24);
        __half2 fh = __floats2half2_rn(f0, f1);
        rec[q].x = (unsigned)(rr[q] * FOUT);
        rec[q].y = (unsigned)(cc[q] * KROW);
        rec[q].z = cells;
        rec[q].w = *(unsigned*)&fh;
        slot[q] = atomicAdd(&g_off[cc[q]], 1) + g_bsum[cc[q] >> 10];
    }
    g_erec[slot[0]] = rec[0];
    g_erec[slot[1]] = rec[1];
    atomicAdd(&g_deg[rr[0]], 1.0f);
    atomicAdd(&g_deg[rr[1]], 1.0f);
}

// ---------------------------------------------------------------------------
// xw_mma (launch 4): xw[n,k,:] = x[n,:] @ W[k]; 512 thr, 256-node tiles.
// ---------------------------------------------------------------------------
__global__ __launch_bounds__(512) void xw_mma() {
    extern __shared__ __half sm[];
    __half* xs = sm;                   // [256][PADR]; reused as epilogue stage
    __half* ws = sm + 256 * PADR;      // [64][PADR]

    const int tid  = threadIdx.x;
    const int wid  = tid >> 5;
    const int lane = tid & 31;
    const int n0   = blockIdx.x * 256;
    const int kbeg = blockIdx.y * 5;
    const int kcnt = (blockIdx.y == 5) ? 1 : 5;

    #pragma unroll
    for (int it = 0; it < 4; it++) {
        int flat = tid + 512 * it;
        int r = flat >> 3, j = flat & 7;
        int gn = n0 + r;
        uint4 v = make_uint4(0, 0, 0, 0);
        if (gn < NN) v = *(const uint4*)(g_xh + (size_t)gn * 64 + j * 8);
        *(uint4*)(xs + r * PADR + j * 8) = v;
    }
    __syncthreads();

    const int m0    = wid * 16;
    const int a_row = m0 + (lane & 15);
    const int a_c8  = (lane >> 4) * 8;
    uint32_t ah[4][4];
    #pragma unroll
    for (int ks = 0; ks < 4; ks++)
        ldsm_x4(smem_u32(xs + a_row * PADR + ks * 16 + a_c8), ah[ks]);

    const int bw_r = lane & 7;
    const int bw_g = lane >> 3;
    const int g  = lane >> 2;
    const int t2 = (lane & 3) * 2;

    for (int j = 0; j < kcnt; j++) {
        const int k = kbeg + j;
        __syncthreads();
        {
            int r = tid >> 3, jc = tid & 7;
            *(uint4*)(ws + r * PADR + jc * 8) =
                *(const uint4*)(g_wt + (k << 12) + r * 64 + jc * 8);
        }
        __syncthreads();

        #pragma unroll
        for (int nt = 0; nt < 8; nt++) {
            float acc[4] = {0.f, 0.f, 0.f, 0.f};
            uint32_t bh[8];
            uint32_t row_off = (nt * 8 + bw_r) * PADR + bw_g * 8;
            ldsm_x4(smem_u32(ws + row_off), bh);
            ldsm_x4(smem_u32(ws + row_off + 32), bh + 4);
            #pragma unroll
            for (int ks = 0; ks < 4; ks++)
                mma_f16(acc, ah[ks], bh + ks * 2);
            __half2 h01 = __floats2half2_rn(acc[0], acc[1]);
            __half2 h23 = __floats2half2_rn(acc[2], acc[3]);
            *(__half2*)(xs + (m0 + g) * PADR + nt * 8 + t2)     = h01;
            *(__half2*)(xs + (m0 + g + 8) * PADR + nt * 8 + t2) = h23;
        }
        __syncthreads();
        #pragma unroll
        for (int it = 0; it < 4; it++) {
            int flat = tid + 512 * it;
            int r = flat >> 3, jc = flat & 7;
            int gn = n0 + r;
            if (gn < NN)
                *(uint4*)(g_xw + (size_t)gn * KROW + k * 64 + jc * 8) =
                    *(const uint4*)(xs + r * PADR + jc * 8);
        }
    }
}

// ---------------------------------------------------------------------------
// edge pass (launch 5): 4 edges/warp (2 per half-warp, batched loads)
// ---------------------------------------------------------------------------
__global__ __launch_bounds__(256) void edge_kernel(float* __restrict__ out) {
    const int warp   = (blockIdx.x * blockDim.x + threadIdx.x) >> 5;
    const int lane   = threadIdx.x & 31;
    const int half   = lane >> 4;
    const int sub4   = (lane & 15) * 4;
    const int nwarps = (gridDim.x * blockDim.x) >> 5;

    for (int e4 = warp * 4; e4 < EE; e4 += nwarps * 4) {
        uint4 ra = g_erec[e4 + half];
        uint4 rb = g_erec[e4 + 2 + half];

        const __half* pa = g_xw + ra.y + sub4;
        const __half* pb = g_xw + rb.y + sub4;
        unsigned ca = ra.z, cb = rb.z;

        uint2 Aa = *(const uint2*)(pa + ((ca & 255u) << 6));
        uint2 Ba = *(const uint2*)(pa + (((ca >> 8) & 255u) << 6));
        uint2 Ca = *(const uint2*)(pa + (((ca >> 16) & 255u) << 6));
        uint2 Da = *(const uint2*)(pa + ((ca >> 24) << 6));
        uint2 Ab = *(const uint2*)(pb + ((cb & 255u) << 6));
        uint2 Bb = *(const uint2*)(pb + (((cb >> 8) & 255u) << 6));
        uint2 Cb = *(const uint2*)(pb + (((cb >> 16) & 255u) << 6));
        uint2 Db = *(const uint2*)(pb + ((cb >> 24) << 6));

        {
            __half2 fh = *(const __half2*)&ra.w;
            float f0 = __low2float(fh), f1 = __high2float(fh);
            float g0 = 1.0f - f0, g1 = 1.0f - f1;
            __half2 w00 = __float2half2_rn(g0 * g1);
            __half2 w10 = __float2half2_rn(f0 * g1);
            __half2 w01 = __float2half2_rn(g0 * f1);
            __half2 w11 = __float2half2_rn(f0 * f1);
            __half2 r0 = __hmul2(w00, *(__half2*)&Aa.x);
            r0 = __hfma2(w10, *(__half2*)&Ba.x, r0);
            r0 = __hfma2(w01, *(__half2*)&Ca.x, r0);
            r0 = __hfma2(w11, *(__half2*)&Da.x, r0);
            __half2 r1 = __hmul2(w00, *(__half2*)&Aa.y);
            r1 = __hfma2(w10, *(__half2*)&Ba.y, r1);
            r1 = __hfma2(w01, *(__half2*)&Ca.y, r1);
            r1 = __hfma2(w11, *(__half2*)&Da.y, r1);
            float2 lo = __half22float2(r0);
            float2 hi = __half22float2(r1);
            float* op = out + ra.x + sub4;
            asm volatile("red.global.add.v4.f32 [%0], {%1, %2, %3, %4};"
                         :: "l"(op), "f"(lo.x), "f"(lo.y), "f"(hi.x), "f"(hi.y)
                         : "memory");
        }
        {
            __half2 fh = *(const __half2*)&rb.w;
            float f0 = __low2float(fh), f1 = __high2float(fh);
            float g0 = 1.0f - f0, g1 = 1.0f - f1;
            __half2 w00 = __float2half2_rn(g0 * g1);
            __half2 w10 = __float2half2_rn(f0 * g1);
            __half2 w01 = __float2half2_rn(g0 * f1);
            __half2 w11 = __float2half2_rn(f0 * f1);
            __half2 r0 = __hmul2(w00, *(__half2*)&Ab.x);
            r0 = __hfma2(w10, *(__half2*)&Bb.x, r0);
            r0 = __hfma2(w01, *(__half2*)&Cb.x, r0);
            r0 = __hfma2(w11, *(__half2*)&Db.x, r0);
            __half2 r1 = __hmul2(w00, *(__half2*)&Ab.y);
            r1 = __hfma2(w10, *(__half2*)&Bb.y, r1);
            r1 = __hfma2(w01, *(__half2*)&Cb.y, r1);
            r1 = __hfma2(w11, *(__half2*)&Db.y, r1);
            float2 lo = __half22float2(r0);
            float2 hi = __half22float2(r1);
            float* op = out + rb.x + sub4;
            asm volatile("red.global.add.v4.f32 [%0], {%1, %2, %3, %4};"
                         :: "l"(op), "f"(lo.x), "f"(lo.y), "f"(hi.x), "f"(hi.y)
                         : "memory");
        }
    }
}

// ---------------------------------------------------------------------------
// final (launch 6): out = out/max(deg,1) + xw[n,25,:] + bias
// ---------------------------------------------------------------------------
__global__ __launch_bounds__(256) void final_kernel(const float* __restrict__ bias,
                                                    float* __restrict__ out) {
    int i = blockIdx.x * 256 + threadIdx.x;
    if (i >= NN * 16) return;
    int n  = i >> 4;
    int c4 = (i & 15) * 4;
    float scale = 1.0f / fmaxf(g_deg[n], 1.0f);
    float4 o = *(float4*)(out + n * FOUT + c4);
    uint2 hu = *(const uint2*)(g_xw + (size_t)n * KROW + KP * 64 + c4);
    float2 rl = __half22float2(*(__half2*)&hu.x);
    float2 rh = __half22float2(*(__half2*)&hu.y);
    float4 b = *(const float4*)(bias + c4);
    o.x = o.x * scale + rl.x + b.x;
    o.y = o.y * scale + rl.y + b.y;
    o.z = o.z * scale + rh.x + b.z;
    o.w = o.w * scale + rh.y + b.w;
    *(float4*)(out + n * FOUT + c4) = o;
}

// ---------------------------------------------------------------------------
extern "C" void kernel_launch(void* const* d_in, const int* in_sizes, int n_in,
                              void* d_out, int out_size) {
    const float* x      = (const float*)d_in[0];
    const int*   ei     = (const int*)  d_in[1];
    const float* pseudo = (const float*)d_in[2];
    const float* weight = (const float*)d_in[3];
    const float* root   = (const float*)d_in[4];
    const float* bias   = (const float*)d_in[5];
    float* out = (float*)d_out;

    const int smem_bytes = (256 * PADR + 64 * PADR) * (int)sizeof(__half);
    cudaFuncSetAttribute(xw_mma, cudaFuncAttributeMaxDynamicSharedMemorySize, smem_bytes);

    fused_prep<<<(NN * 64 + 255) / 256, 256>>>(x, weight, root, ei, out);  // 0
    scan_local<<<NBLK, 1024>>>();                                          // 1
    scan_tops<<<1, 64>>>();                                                // 2
    prep_edges<<<(EE / 2 + 255) / 256, 256>>>(ei, pseudo);                 // 3 <- ncu
    dim3 g2((NN + 255) / 256, 6);
    xw_mma<<<g2, 512, smem_bytes>>>();                                     // 4
    edge_kernel<<<6144, 256>>>(out);                                       // 5
    final_kernel<<<(NN * 16 + 255) / 256, 256>>>(bias, out);               // 6
}

// round 14
// speedup vs baseline: 1.2056x; 1.1352x over previous
#include <cuda_runtime.h>
#include <cuda_fp16.h>
#include <cstdint>

#define NN    50000
#define EE    1600000
#define KP    25
#define KALL  26                    // 25 spline mats + root
#define FOUT  64
#define KROW  (KALL * FOUT)         // 1664 halves per node row
#define PADR  72                    // row pad (half): 144B rows, LDSM conflict-free
#define NBLK  ((NN + 1023) / 1024)  // scan blocks

// ---------------- device scratch (no runtime allocation allowed) -----------
__device__ __half g_xh[(size_t)NN * 64];
__device__ __half g_wt[KALL * 64 * 64];          // fp16 W^T: [k][o][i], k=25 is root
__device__ __half g_xw[(size_t)NN * KROW];       // 166 MB fp16 table
__device__ __half g_acc[(size_t)NN * 64];        // fp16 edge accumulator
__device__ float  g_deg[NN];
__device__ int    g_cnt[NN];                     // zero-init; re-zeroed by scan_local
__device__ int    g_off[NN];
__device__ int    g_bsum[NBLK];
__device__ uint4  g_erec[EE];                    // edge records (col-sorted)

// ---------------- helpers ---------------------------------------------------
__device__ __forceinline__ uint32_t smem_u32(const void* p) {
    uint32_t a;
    asm("{ .reg .u64 t; cvta.to.shared.u64 t, %1; cvt.u32.u64 %0, t; }"
        : "=r"(a) : "l"(p));
    return a;
}
__device__ __forceinline__ void ldsm_x4(uint32_t addr, uint32_t* r) {
    asm volatile("ldmatrix.sync.aligned.m8n8.x4.shared.b16 {%0,%1,%2,%3}, [%4];"
                 : "=r"(r[0]), "=r"(r[1]), "=r"(r[2]), "=r"(r[3]) : "r"(addr));
}
__device__ __forceinline__ void mma_f16(float* c, const uint32_t* a, const uint32_t* b) {
    asm volatile(
        "mma.sync.aligned.m16n8k16.row.col.f32.f16.f16.f32 "
        "{%0,%1,%2,%3}, {%4,%5,%6,%7}, {%8,%9}, {%0,%1,%2,%3};"
        : "+f"(c[0]), "+f"(c[1]), "+f"(c[2]), "+f"(c[3])
        : "r"(a[0]), "r"(a[1]), "r"(a[2]), "r"(a[3]), "r"(b[0]), "r"(b[1]));
}

// ---------------------------------------------------------------------------
// fused prep (launch 0): x->fp16, acc zero, deg zero, W^T->fp16, col histogram
// ---------------------------------------------------------------------------
__global__ __launch_bounds__(256) void fused_prep(const float* __restrict__ x,
                                                  const float* __restrict__ w,
                                                  const float* __restrict__ root,
                                                  const int*   __restrict__ ei) {
    int i = blockIdx.x * blockDim.x + threadIdx.x;
    if (i < NN * 64) {
        g_xh[i] = __float2half(x[i]);
        g_acc[i] = __ushort_as_half(0);
    }
    if (i < NN) g_deg[i] = 0.0f;
    if (i < KALL * 64 * 64) {
        int k = i >> 12, rem = i & 4095;
        int ii = rem >> 6, o = rem & 63;
        float v = (k < KP) ? w[i] : root[rem];
        g_wt[(k << 12) + (o << 6) + ii] = __float2half(v);   // [k][o][i]
    }
    if (i < EE) atomicAdd(&g_cnt[ei[EE + i]], 1);
}

// ---- scan (launches 1,2): local shuffle scan (+cnt reset) -> tops scan ----
__global__ __launch_bounds__(1024) void scan_local() {
    __shared__ int wsum[32];
    int idx  = blockIdx.x * 1024 + threadIdx.x;
    int lane = threadIdx.x & 31;
    int wid  = threadIdx.x >> 5;
    int v = (idx < NN) ? g_cnt[idx] : 0;
    if (idx < NN) g_cnt[idx] = 0;                // reset for next launch/replay
    int s = v;
    #pragma unroll
    for (int o = 1; o < 32; o <<= 1) {
        int t = __shfl_up_sync(0xFFFFFFFFu, s, o);
        if (lane >= o) s += t;
    }
    if (lane == 31) wsum[wid] = s;
    __syncthreads();
    if (wid == 0) {
        int ws = wsum[lane];
        #pragma unroll
        for (int o = 1; o < 32; o <<= 1) {
            int t = __shfl_up_sync(0xFFFFFFFFu, ws, o);
            if (lane >= o) ws += t;
        }
        wsum[lane] = ws;
    }
    __syncthreads();
    int excl = s - v + (wid > 0 ? wsum[wid - 1] : 0);
    if (idx < NN) g_off[idx] = excl;             // block-local exclusive prefix
    if (threadIdx.x == 1023) g_bsum[blockIdx.x] = excl + v;
}
__global__ __launch_bounds__(64) void scan_tops() {
    __shared__ int s[64];
    int tid = threadIdx.x;
    s[tid] = (tid < NBLK) ? g_bsum[tid] : 0;
    __syncthreads();
    if (tid == 0) {
        int acc = 0;
        #pragma unroll 1
        for (int i = 0; i < NBLK; i++) { int t = s[i]; s[i] = acc; acc += t; }
    }
    __syncthreads();
    if (tid < NBLK) g_bsum[tid] = s[tid];
}

// ---------------------------------------------------------------------------
// prep_edges (launch 3): 2 edges/thread, batched loads, col-sorted scatter.
// ---------------------------------------------------------------------------
__global__ __launch_bounds__(256) void prep_edges(const int* __restrict__ ei,
                                                  const float* __restrict__ ps) {
    int e0 = (blockIdx.x * 256 + threadIdx.x) * 2;
    if (e0 >= EE) return;
    int2   rows = *(const int2*)(ei + e0);
    int2   cols = *(const int2*)(ei + EE + e0);
    float4 pp   = *(const float4*)(ps + 2 * e0);

    int   rr[2] = {rows.x, rows.y};
    int   cc[2] = {cols.x, cols.y};
    float px[2] = {pp.x, pp.z};
    float py[2] = {pp.y, pp.w};

    uint4 rec[2];
    int   slot[2];
    #pragma unroll
    for (int q = 0; q < 2; q++) {
        float v0 = px[q] * 4.0f, v1 = py[q] * 4.0f;
        float fl0 = floorf(v0), fl1 = floorf(v1);
        float f0 = v0 - fl0, f1 = v1 - fl1;
        int i0 = (int)fl0, i1 = (int)fl1;        // 0..3, +1 in range
        unsigned c00 = (unsigned)(i0 * 5 + i1);
        unsigned cells = c00 | ((c00 + 5u) << 8) | ((c00 + 1u) << 16) | ((c00 + 6u) << 24);
        __half2 fh = __floats2half2_rn(f0, f1);
        rec[q].x = (unsigned)(rr[q] * FOUT);
        rec[q].y = (unsigned)(cc[q] * KROW);
        rec[q].z = cells;
        rec[q].w = *(unsigned*)&fh;
        slot[q] = atomicAdd(&g_off[cc[q]], 1) + g_bsum[cc[q] >> 10];
    }
    g_erec[slot[0]] = rec[0];
    g_erec[slot[1]] = rec[1];
    atomicAdd(&g_deg[rr[0]], 1.0f);
    atomicAdd(&g_deg[rr[1]], 1.0f);
}

// ---------------------------------------------------------------------------
// xw_mma (launch 4): xw[n,k,:] = x[n,:] @ W[k]; 512 thr, 256-node tiles.
// ---------------------------------------------------------------------------
__global__ __launch_bounds__(512) void xw_mma() {
    extern __shared__ __half sm[];
    __half* xs = sm;                   // [256][PADR]; reused as epilogue stage
    __half* ws = sm + 256 * PADR;      // [64][PADR]

    const int tid  = threadIdx.x;
    const int wid  = tid >> 5;
    const int lane = tid & 31;
    const int n0   = blockIdx.x * 256;
    const int kbeg = blockIdx.y * 5;
    const int kcnt = (blockIdx.y == 5) ? 1 : 5;

    #pragma unroll
    for (int it = 0; it < 4; it++) {
        int flat = tid + 512 * it;
        int r = flat >> 3, j = flat & 7;
        int gn = n0 + r;
        uint4 v = make_uint4(0, 0, 0, 0);
        if (gn < NN) v = *(const uint4*)(g_xh + (size_t)gn * 64 + j * 8);
        *(uint4*)(xs + r * PADR + j * 8) = v;
    }
    __syncthreads();

    const int m0    = wid * 16;
    const int a_row = m0 + (lane & 15);
    const int a_c8  = (lane >> 4) * 8;
    uint32_t ah[4][4];
    #pragma unroll
    for (int ks = 0; ks < 4; ks++)
        ldsm_x4(smem_u32(xs + a_row * PADR + ks * 16 + a_c8), ah[ks]);

    const int bw_r = lane & 7;
    const int bw_g = lane >> 3;
    const int g  = lane >> 2;
    const int t2 = (lane & 3) * 2;

    for (int j = 0; j < kcnt; j++) {
        const int k = kbeg + j;
        __syncthreads();
        {
            int r = tid >> 3, jc = tid & 7;
            *(uint4*)(ws + r * PADR + jc * 8) =
                *(const uint4*)(g_wt + (k << 12) + r * 64 + jc * 8);
        }
        __syncthreads();

        #pragma unroll
        for (int nt = 0; nt < 8; nt++) {
            float acc[4] = {0.f, 0.f, 0.f, 0.f};
            uint32_t bh[8];
            uint32_t row_off = (nt * 8 + bw_r) * PADR + bw_g * 8;
            ldsm_x4(smem_u32(ws + row_off), bh);
            ldsm_x4(smem_u32(ws + row_off + 32), bh + 4);
            #pragma unroll
            for (int ks = 0; ks < 4; ks++)
                mma_f16(acc, ah[ks], bh + ks * 2);
            __half2 h01 = __floats2half2_rn(acc[0], acc[1]);
            __half2 h23 = __floats2half2_rn(acc[2], acc[3]);
            *(__half2*)(xs + (m0 + g) * PADR + nt * 8 + t2)     = h01;
            *(__half2*)(xs + (m0 + g + 8) * PADR + nt * 8 + t2) = h23;
        }
        __syncthreads();
        #pragma unroll
        for (int it = 0; it < 4; it++) {
            int flat = tid + 512 * it;
            int r = flat >> 3, jc = flat & 7;
            int gn = n0 + r;
            if (gn < NN)
                *(uint4*)(g_xw + (size_t)gn * KROW + k * 64 + jc * 8) =
                    *(const uint4*)(xs + r * PADR + jc * 8);
        }
    }
}

// ---------------------------------------------------------------------------
// edge pass (launch 5): quarter-warp (8 lanes x 8 cols) per edge; fp16 blend;
// red.global.add.noftz.v4.f16x2 into g_acc (8 atomic ops/edge, was 16)
// ---------------------------------------------------------------------------
__global__ __launch_bounds__(256) void edge_kernel() {
    const int warp   = (blockIdx.x * blockDim.x + threadIdx.x) >> 5;
    const int lane   = threadIdx.x & 31;
    const int quart  = lane >> 3;          // which edge of the 4
    const int sub8   = (lane & 7) * 8;     // 8 halves per lane
    const int nwarps = (gridDim.x * blockDim.x) >> 5;

    for (int e4 = warp * 4; e4 < EE; e4 += nwarps * 4) {
        uint4 rec = g_erec[e4 + quart];
        const __half* p = g_xw + rec.y + sub8;
        unsigned c = rec.z;

        uint4 A = *(const uint4*)(p + ((c & 255u) << 6));
        uint4 B = *(const uint4*)(p + (((c >> 8) & 255u) << 6));
        uint4 C = *(const uint4*)(p + (((c >> 16) & 255u) << 6));
        uint4 D = *(const uint4*)(p + ((c >> 24) << 6));

        __half2 fh = *(const __half2*)&rec.w;
        float f0 = __low2float(fh), f1 = __high2float(fh);
        float g0 = 1.0f - f0, g1 = 1.0f - f1;
        __half2 w00 = __float2half2_rn(g0 * g1);
        __half2 w10 = __float2half2_rn(f0 * g1);
        __half2 w01 = __float2half2_rn(g0 * f1);
        __half2 w11 = __float2half2_rn(f0 * f1);

        __half2 r0 = __hmul2(w00, *(__half2*)&A.x);
        r0 = __hfma2(w10, *(__half2*)&B.x, r0);
        r0 = __hfma2(w01, *(__half2*)&C.x, r0);
        r0 = __hfma2(w11, *(__half2*)&D.x, r0);
        __half2 r1 = __hmul2(w00, *(__half2*)&A.y);
        r1 = __hfma2(w10, *(__half2*)&B.y, r1);
        r1 = __hfma2(w01, *(__half2*)&C.y, r1);
        r1 = __hfma2(w11, *(__half2*)&D.y, r1);
        __half2 r2 = __hmul2(w00, *(__half2*)&A.z);
        r2 = __hfma2(w10, *(__half2*)&B.z, r2);
        r2 = __hfma2(w01, *(__half2*)&C.z, r2);
        r2 = __hfma2(w11, *(__half2*)&D.z, r2);
        __half2 r3 = __hmul2(w00, *(__half2*)&A.w);
        r3 = __hfma2(w10, *(__half2*)&B.w, r3);
        r3 = __hfma2(w01, *(__half2*)&C.w, r3);
        r3 = __hfma2(w11, *(__half2*)&D.w, r3);

        __half* op = g_acc + rec.x + sub8;
        asm volatile("red.global.add.noftz.v4.f16x2 [%0], {%1, %2, %3, %4};"
                     :: "l"(op),
                        "r"(*(unsigned*)&r0), "r"(*(unsigned*)&r1),
                        "r"(*(unsigned*)&r2), "r"(*(unsigned*)&r3)
                     : "memory");
    }
}

// ---------------------------------------------------------------------------
// final (launch 6): out = acc/max(deg,1) + xw[n,25,:] + bias
// ---------------------------------------------------------------------------
__global__ __launch_bounds__(256) void final_kernel(const float* __restrict__ bias,
                                                    float* __restrict__ out) {
    int i = blockIdx.x * 256 + threadIdx.x;
    if (i >= NN * 16) return;
    int n  = i >> 4;
    int c4 = (i & 15) * 4;
    float scale = 1.0f / fmaxf(g_deg[n], 1.0f);
    uint2 au = *(const uint2*)(g_acc + (size_t)n * 64 + c4);
    float2 al = __half22float2(*(__half2*)&au.x);
    float2 ah = __half22float2(*(__half2*)&au.y);
    uint2 hu = *(const uint2*)(g_xw + (size_t)n * KROW + KP * 64 + c4);
    float2 rl = __half22float2(*(__half2*)&hu.x);
    float2 rh = __half22float2(*(__half2*)&hu.y);
    float4 b = *(const float4*)(bias + c4);
    float4 o;
    o.x = al.x * scale + rl.x + b.x;
    o.y = al.y * scale + rl.y + b.y;
    o.z = ah.x * scale + rh.x + b.z;
    o.w = ah.y * scale + rh.y + b.w;
    *(float4*)(out + n * FOUT + c4) = o;
}

// ---------------------------------------------------------------------------
extern "C" void kernel_launch(void* const* d_in, const int* in_sizes, int n_in,
                              void* d_out, int out_size) {
    const float* x      = (const float*)d_in[0];
    const int*   ei     = (const int*)  d_in[1];
    const float* pseudo = (const float*)d_in[2];
    const float* weight = (const float*)d_in[3];
    const float* root   = (const float*)d_in[4];
    const float* bias   = (const float*)d_in[5];
    float* out = (float*)d_out;

    const int smem_bytes = (256 * PADR + 64 * PADR) * (int)sizeof(__half);
    cudaFuncSetAttribute(xw_mma, cudaFuncAttributeMaxDynamicSharedMemorySize, smem_bytes);

    fused_prep<<<(NN * 64 + 255) / 256, 256>>>(x, weight, root, ei);       // 0
    scan_local<<<NBLK, 1024>>>();                                          // 1
    scan_tops<<<1, 64>>>();                                                // 2
    prep_edges<<<(EE / 2 + 255) / 256, 256>>>(ei, pseudo);                 // 3
    dim3 g2((NN + 255) / 256, 6);
    xw_mma<<<g2, 512, smem_bytes>>>();                                     // 4
    edge_kernel<<<6144, 256>>>();                                          // 5
    final_kernel<<<(NN * 16 + 255) / 256, 256>>>(bias, out);               // 6
}

// round 15
// speedup vs baseline: 1.2671x; 1.0510x over previous
#include <cuda_runtime.h>
#include <cuda_fp16.h>
#include <cstdint>

#define NN    50000
#define EE    1600000
#define KP    25
#define KALL  26                    // 25 spline mats + root
#define FOUT  64
#define KROW  (KALL * FOUT)         // 1664 halves per node row
#define PADR  72                    // row pad (half): 144B rows, LDSM conflict-free
#define NBLK  ((NN + 1023) / 1024)  // scan blocks

// ---------------- device scratch (no runtime allocation allowed) -----------
__device__ __half g_xh[(size_t)NN * 64];
__device__ __half g_wt[KALL * 64 * 64];          // fp16 W^T: [k][o][i], k=25 is root
__device__ __half g_xw[(size_t)NN * KROW];       // 166 MB fp16 table
__device__ __half g_acc[(size_t)NN * 64];        // fp16 edge accumulator
__device__ float  g_deg[NN];
__device__ int    g_cnt[NN];                     // zero-init; re-zeroed by scan_local
__device__ int    g_off[NN];
__device__ int    g_bsum[NBLK];
__device__ uint4  g_erec[EE];                    // edge records (col-sorted)

// ---------------- helpers ---------------------------------------------------
__device__ __forceinline__ uint32_t smem_u32(const void* p) {
    uint32_t a;
    asm("{ .reg .u64 t; cvta.to.shared.u64 t, %1; cvt.u32.u64 %0, t; }"
        : "=r"(a) : "l"(p));
    return a;
}
__device__ __forceinline__ void ldsm_x4(uint32_t addr, uint32_t* r) {
    asm volatile("ldmatrix.sync.aligned.m8n8.x4.shared.b16 {%0,%1,%2,%3}, [%4];"
                 : "=r"(r[0]), "=r"(r[1]), "=r"(r[2]), "=r"(r[3]) : "r"(addr));
}
// fp16-accumulate MMA: C/D are 2x f16x2 regs
__device__ __forceinline__ void mma_f16acc(uint32_t* c, const uint32_t* a,
                                           const uint32_t* b) {
    asm volatile(
        "mma.sync.aligned.m16n8k16.row.col.f16.f16.f16.f16 "
        "{%0,%1}, {%2,%3,%4,%5}, {%6,%7}, {%0,%1};"
        : "+r"(c[0]), "+r"(c[1])
        : "r"(a[0]), "r"(a[1]), "r"(a[2]), "r"(a[3]), "r"(b[0]), "r"(b[1]));
}

// ---------------------------------------------------------------------------
// fused prep (launch 0): x->fp16, acc zero, deg zero, W^T->fp16, col histogram
// ---------------------------------------------------------------------------
__global__ __launch_bounds__(256) void fused_prep(const float* __restrict__ x,
                                                  const float* __restrict__ w,
                                                  const float* __restrict__ root,
                                                  const int*   __restrict__ ei) {
    int i = blockIdx.x * blockDim.x + threadIdx.x;
    if (i < NN * 64) {
        g_xh[i] = __float2half(x[i]);
        g_acc[i] = __ushort_as_half(0);
    }
    if (i < NN) g_deg[i] = 0.0f;
    if (i < KALL * 64 * 64) {
        int k = i >> 12, rem = i & 4095;
        int ii = rem >> 6, o = rem & 63;
        float v = (k < KP) ? w[i] : root[rem];
        g_wt[(k << 12) + (o << 6) + ii] = __float2half(v);   // [k][o][i]
    }
    if (i < EE) atomicAdd(&g_cnt[ei[EE + i]], 1);
}

// ---- scan (launches 1,2): local shuffle scan (+cnt reset) -> tops scan ----
__global__ __launch_bounds__(1024) void scan_local() {
    __shared__ int wsum[32];
    int idx  = blockIdx.x * 1024 + threadIdx.x;
    int lane = threadIdx.x & 31;
    int wid  = threadIdx.x >> 5;
    int v = (idx < NN) ? g_cnt[idx] : 0;
    if (idx < NN) g_cnt[idx] = 0;                // reset for next launch/replay
    int s = v;
    #pragma unroll
    for (int o = 1; o < 32; o <<= 1) {
        int t = __shfl_up_sync(0xFFFFFFFFu, s, o);
        if (lane >= o) s += t;
    }
    if (lane == 31) wsum[wid] = s;
    __syncthreads();
    if (wid == 0) {
        int ws = wsum[lane];
        #pragma unroll
        for (int o = 1; o < 32; o <<= 1) {
            int t = __shfl_up_sync(0xFFFFFFFFu, ws, o);
            if (lane >= o) ws += t;
        }
        wsum[lane] = ws;
    }
    __syncthreads();
    int excl = s - v + (wid > 0 ? wsum[wid - 1] : 0);
    if (idx < NN) g_off[idx] = excl;             // block-local exclusive prefix
    if (threadIdx.x == 1023) g_bsum[blockIdx.x] = excl + v;
}
__global__ __launch_bounds__(64) void scan_tops() {
    __shared__ int s[64];
    int tid = threadIdx.x;
    s[tid] = (tid < NBLK) ? g_bsum[tid] : 0;
    __syncthreads();
    if (tid == 0) {
        int acc = 0;
        #pragma unroll 1
        for (int i = 0; i < NBLK; i++) { int t = s[i]; s[i] = acc; acc += t; }
    }
    __syncthreads();
    if (tid < NBLK) g_bsum[tid] = s[tid];
}

// ---------------------------------------------------------------------------
// xw_mma (launch 3 <- ncu): xw[n,k,:] = x[n,:] @ W[k]; 256 thr, 128-row tile,
// warp tiles 32M x 32N (halved B-LDSM), fp16-accumulate MMA.
// ---------------------------------------------------------------------------
__global__ __launch_bounds__(256) void xw_mma() {
    extern __shared__ __half sm[];
    __half* xs = sm;                   // [128][PADR]; reused as epilogue stage
    __half* ws = sm + 128 * PADR;      // [64][PADR]

    const int tid  = threadIdx.x;
    const int wid  = tid >> 5;
    const int lane = tid & 31;
    const int wm   = wid & 3;          // 4 M-groups of 32 rows
    const int wn   = wid >> 2;         // 2 N-groups of 32 cols
    const int n0   = blockIdx.x * 128;
    const int kbeg = blockIdx.y * 5;
    const int kcnt = (blockIdx.y == 5) ? 1 : 5;

    // load x tile (128 rows x 8 uint4)
    #pragma unroll
    for (int it = 0; it < 4; it++) {
        int flat = tid + 256 * it;
        int r = flat >> 3, j = flat & 7;
        int gn = n0 + r;
        uint4 v = make_uint4(0, 0, 0, 0);
        if (gn < NN) v = *(const uint4*)(g_xh + (size_t)gn * 64 + j * 8);
        *(uint4*)(xs + r * PADR + j * 8) = v;
    }
    __syncthreads();

    // hoist A fragments: 2 m16-tiles x 4 ks
    const int a_c8 = (lane >> 4) * 8;
    uint32_t ah[2][4][4];
    #pragma unroll
    for (int mt = 0; mt < 2; mt++) {
        int a_row = wm * 32 + mt * 16 + (lane & 15);
        #pragma unroll
        for (int ks = 0; ks < 4; ks++)
            ldsm_x4(smem_u32(xs + a_row * PADR + ks * 16 + a_c8), ah[mt][ks]);
    }

    const int bw_r = lane & 7;
    const int bw_g = lane >> 3;
    const int g  = lane >> 2;
    const int t2 = (lane & 3) * 2;

    for (int j = 0; j < kcnt; j++) {
        const int k = kbeg + j;
        __syncthreads();
        // load W^T[k] (64 rows x 8 uint4, 2 per thread)
        #pragma unroll
        for (int it = 0; it < 2; it++) {
            int flat = tid + 256 * it;
            int r = flat >> 3, jc = flat & 7;
            *(uint4*)(ws + r * PADR + jc * 8) =
                *(const uint4*)(g_wt + (k << 12) + r * 64 + jc * 8);
        }
        __syncthreads();

        #pragma unroll
        for (int nt = 0; nt < 4; nt++) {
            int ncol = wn * 32 + nt * 8;
            uint32_t bh[8];
            uint32_t row_off = (ncol + bw_r) * PADR + bw_g * 8;
            ldsm_x4(smem_u32(ws + row_off), bh);
            ldsm_x4(smem_u32(ws + row_off + 32), bh + 4);
            #pragma unroll
            for (int mt = 0; mt < 2; mt++) {
                uint32_t acc[2] = {0u, 0u};
                #pragma unroll
                for (int ks = 0; ks < 4; ks++)
                    mma_f16acc(acc, ah[mt][ks], bh + ks * 2);
                int mrow = wm * 32 + mt * 16 + g;
                *(uint32_t*)(xs + mrow * PADR + ncol + t2)       = acc[0];
                *(uint32_t*)(xs + (mrow + 8) * PADR + ncol + t2) = acc[1];
            }
        }
        __syncthreads();
        // coalesced copy-out: 128 rows x 128B
        #pragma unroll
        for (int it = 0; it < 4; it++) {
            int flat = tid + 256 * it;
            int r = flat >> 3, jc = flat & 7;
            int gn = n0 + r;
            if (gn < NN)
                *(uint4*)(g_xw + (size_t)gn * KROW + k * 64 + jc * 8) =
                    *(const uint4*)(xs + r * PADR + jc * 8);
        }
    }
}

// ---------------------------------------------------------------------------
// prep_edges (launch 4): 2 edges/thread, batched loads, col-sorted scatter.
// ---------------------------------------------------------------------------
__global__ __launch_bounds__(256) void prep_edges(const int* __restrict__ ei,
                                                  const float* __restrict__ ps) {
    int e0 = (blockIdx.x * 256 + threadIdx.x) * 2;
    if (e0 >= EE) return;
    int2   rows = *(const int2*)(ei + e0);
    int2   cols = *(const int2*)(ei + EE + e0);
    float4 pp   = *(const float4*)(ps + 2 * e0);

    int   rr[2] = {rows.x, rows.y};
    int   cc[2] = {cols.x, cols.y};
    float px[2] = {pp.x, pp.z};
    float py[2] = {pp.y, pp.w};

    uint4 rec[2];
    int   slot[2];
    #pragma unroll
    for (int q = 0; q < 2; q++) {
        float v0 = px[q] * 4.0f, v1 = py[q] * 4.0f;
        float fl0 = floorf(v0), fl1 = floorf(v1);
        float f0 = v0 - fl0, f1 = v1 - fl1;
        int i0 = (int)fl0, i1 = (int)fl1;        // 0..3, +1 in range
        unsigned c00 = (unsigned)(i0 * 5 + i1);
        unsigned cells = c00 | ((c00 + 5u) << 8) | ((c00 + 1u) << 16) | ((c00 + 6u) << 24);
        __half2 fh = __floats2half2_rn(f0, f1);
        rec[q].x = (unsigned)(rr[q] * FOUT);
        rec[q].y = (unsigned)(cc[q] * KROW);
        rec[q].z = cells;
        rec[q].w = *(unsigned*)&fh;
        slot[q] = atomicAdd(&g_off[cc[q]], 1) + g_bsum[cc[q] >> 10];
    }
    g_erec[slot[0]] = rec[0];
    g_erec[slot[1]] = rec[1];
    atomicAdd(&g_deg[rr[0]], 1.0f);
    atomicAdd(&g_deg[rr[1]], 1.0f);
}

// ---------------------------------------------------------------------------
// edge pass (launch 5): quarter-warp (8 lanes x 8 cols) per edge; fp16 blend;
// red.global.add.noftz.v4.f16x2 into g_acc (8 atomic ops/edge)
// ---------------------------------------------------------------------------
__global__ __launch_bounds__(256) void edge_kernel() {
    const int warp   = (blockIdx.x * blockDim.x + threadIdx.x) >> 5;
    const int lane   = threadIdx.x & 31;
    const int quart  = lane >> 3;          // which edge of the 4
    const int sub8   = (lane & 7) * 8;     // 8 halves per lane
    const int nwarps = (gridDim.x * blockDim.x) >> 5;

    for (int e4 = warp * 4; e4 < EE; e4 += nwarps * 4) {
        uint4 rec = g_erec[e4 + quart];
        const __half* p = g_xw + rec.y + sub8;
        unsigned c = rec.z;

        uint4 A = *(const uint4*)(p + ((c & 255u) << 6));
        uint4 B = *(const uint4*)(p + (((c >> 8) & 255u) << 6));
        uint4 C = *(const uint4*)(p + (((c >> 16) & 255u) << 6));
        uint4 D = *(const uint4*)(p + ((c >> 24) << 6));

        __half2 fh = *(const __half2*)&rec.w;
        float f0 = __low2float(fh), f1 = __high2float(fh);
        float g0 = 1.0f - f0, g1 = 1.0f - f1;
        __half2 w00 = __float2half2_rn(g0 * g1);
        __half2 w10 = __float2half2_rn(f0 * g1);
        __half2 w01 = __float2half2_rn(g0 * f1);
        __half2 w11 = __float2half2_rn(f0 * f1);

        __half2 r0 = __hmul2(w00, *(__half2*)&A.x);
        r0 = __hfma2(w10, *(__half2*)&B.x, r0);
        r0 = __hfma2(w01, *(__half2*)&C.x, r0);
        r0 = __hfma2(w11, *(__half2*)&D.x, r0);
        __half2 r1 = __hmul2(w00, *(__half2*)&A.y);
        r1 = __hfma2(w10, *(__half2*)&B.y, r1);
        r1 = __hfma2(w01, *(__half2*)&C.y, r1);
        r1 = __hfma2(w11, *(__half2*)&D.y, r1);
        __half2 r2 = __hmul2(w00, *(__half2*)&A.z);
        r2 = __hfma2(w10, *(__half2*)&B.z, r2);
        r2 = __hfma2(w01, *(__half2*)&C.z, r2);
        r2 = __hfma2(w11, *(__half2*)&D.z, r2);
        __half2 r3 = __hmul2(w00, *(__half2*)&A.w);
        r3 = __hfma2(w10, *(__half2*)&B.w, r3);
        r3 = __hfma2(w01, *(__half2*)&C.w, r3);
        r3 = __hfma2(w11, *(__half2*)&D.w, r3);

        __half* op = g_acc + rec.x + sub8;
        asm volatile("red.global.add.noftz.v4.f16x2 [%0], {%1, %2, %3, %4};"
                     :: "l"(op),
                        "r"(*(unsigned*)&r0), "r"(*(unsigned*)&r1),
                        "r"(*(unsigned*)&r2), "r"(*(unsigned*)&r3)
                     : "memory");
    }
}

// ---------------------------------------------------------------------------
// final (launch 6): out = acc/max(deg,1) + xw[n,25,:] + bias
// ---------------------------------------------------------------------------
__global__ __launch_bounds__(256) void final_kernel(const float* __restrict__ bias,
                                                    float* __restrict__ out) {
    int i = blockIdx.x * 256 + threadIdx.x;
    if (i >= NN * 16) return;
    int n  = i >> 4;
    int c4 = (i & 15) * 4;
    float scale = 1.0f / fmaxf(g_deg[n], 1.0f);
    uint2 au = *(const uint2*)(g_acc + (size_t)n * 64 + c4);
    float2 al = __half22float2(*(__half2*)&au.x);
    float2 ah = __half22float2(*(__half2*)&au.y);
    uint2 hu = *(const uint2*)(g_xw + (size_t)n * KROW + KP * 64 + c4);
    float2 rl = __half22float2(*(__half2*)&hu.x);
    float2 rh = __half22float2(*(__half2*)&hu.y);
    float4 b = *(const float4*)(bias + c4);
    float4 o;
    o.x = al.x * scale + rl.x + b.x;
    o.y = al.y * scale + rl.y + b.y;
    o.z = ah.x * scale + rh.x + b.z;
    o.w = ah.y * scale + rh.y + b.w;
    *(float4*)(out + n * FOUT + c4) = o;
}

// ---------------------------------------------------------------------------
extern "C" void kernel_launch(void* const* d_in, const int* in_sizes, int n_in,
                              void* d_out, int out_size) {
    const float* x      = (const float*)d_in[0];
    const int*   ei     = (const int*)  d_in[1];
    const float* pseudo = (const float*)d_in[2];
    const float* weight = (const float*)d_in[3];
    const float* root   = (const float*)d_in[4];
    const float* bias   = (const float*)d_in[5];
    float* out = (float*)d_out;

    const int smem_bytes = (128 * PADR + 64 * PADR) * (int)sizeof(__half);
    cudaFuncSetAttribute(xw_mma, cudaFuncAttributeMaxDynamicSharedMemorySize, smem_bytes);

    fused_prep<<<(NN * 64 + 255) / 256, 256>>>(x, weight, root, ei);       // 0
    scan_local<<<NBLK, 1024>>>();                                          // 1
    scan_tops<<<1, 64>>>();                                                // 2
    dim3 g2((NN + 127) / 128, 6);
    xw_mma<<<g2, 256, smem_bytes>>>();                                     // 3 <- ncu
    prep_edges<<<(EE / 2 + 255) / 256, 256>>>(ei, pseudo);                 // 4
    edge_kernel<<<6144, 256>>>();                                          // 5
    final_kernel<<<(NN * 16 + 255) / 256, 256>>>(bias, out);               // 6
}